// round 2
// baseline (speedup 1.0000x reference)
#include <cuda_runtime.h>

// Problem constants
#define SS 4096
#define HH 1024
#define II 1024
#define G4 4096   // 4*H

#define NCTA_DIR 74
#define UPC 14            // hidden units per CTA (74*14 = 1036 >= 1024)
#define REC_THREADS 448   // 14 warps, one unit per warp
#define REC_SMEM (UPC*4*1024*4)  // 229376 bytes

// Persistent device scratch (allocation-free rule: __device__ globals)
__device__ float g_xp[2][SS][G4];       // x_proj per direction, 128 MB
__device__ float g_h[2][2][HH];         // double-buffered hidden state per direction
__device__ unsigned g_count[2];         // barrier arrival counters (self-resetting)
__device__ volatile unsigned g_phase[2];// barrier phase flags (restored each launch)

// ---------------------------------------------------------------------------
// GEMM: x_proj[dir][s][r] = sum_k inputs[s][k] * W[r][1024+k] + b[r]
// 128x128 block tile, BK=8, 256 threads, 8x8 per-thread micro-tile,
// double-buffered SMEM with transpose-on-store (+4 pad kills STS conflicts).
// ---------------------------------------------------------------------------
__global__ void __launch_bounds__(256, 2) xproj_kernel(
    const float* __restrict__ inp,
    const float* __restrict__ W0, const float* __restrict__ b0,
    const float* __restrict__ W1, const float* __restrict__ b1)
{
    const int dir = blockIdx.z;
    const float* __restrict__ W    = dir ? W1 : W0;
    const float* __restrict__ bias = dir ? b1 : b0;
    float* __restrict__ out = &g_xp[dir][0][0];

    const int bm = blockIdx.y, bn = blockIdx.x;
    const int tid = threadIdx.x;
    const int tx = tid & 15, ty = tid >> 4;

    __shared__ float As[2][8][132];
    __shared__ float Bs[2][8][132];

    const int lr = tid >> 1;         // 0..127
    const int lk = (tid & 1) << 2;   // 0 or 4

    const float* Ap = inp + (size_t)(bm * 128 + lr) * 1024 + lk;
    const float* Bp = W   + (size_t)(bn * 128 + lr) * 2048 + 1024 + lk;

    float4 av = *(const float4*)Ap;
    float4 bv = *(const float4*)Bp;
    As[0][lk + 0][lr] = av.x; As[0][lk + 1][lr] = av.y;
    As[0][lk + 2][lr] = av.z; As[0][lk + 3][lr] = av.w;
    Bs[0][lk + 0][lr] = bv.x; Bs[0][lk + 1][lr] = bv.y;
    Bs[0][lk + 2][lr] = bv.z; Bs[0][lk + 3][lr] = bv.w;
    __syncthreads();

    float acc[8][8];
#pragma unroll
    for (int i = 0; i < 8; i++)
#pragma unroll
        for (int j = 0; j < 8; j++) acc[i][j] = 0.f;

    for (int kt = 0; kt < 128; kt++) {
        const int cur = kt & 1;
        if (kt < 127) {
            av = *(const float4*)(Ap + (kt + 1) * 8);
            bv = *(const float4*)(Bp + (kt + 1) * 8);
        }
#pragma unroll
        for (int k = 0; k < 8; k++) {
            float ar[8], bc[8];
            *(float4*)&ar[0] = *(const float4*)&As[cur][k][ty * 4];
            *(float4*)&ar[4] = *(const float4*)&As[cur][k][64 + ty * 4];
            *(float4*)&bc[0] = *(const float4*)&Bs[cur][k][tx * 4];
            *(float4*)&bc[4] = *(const float4*)&Bs[cur][k][64 + tx * 4];
#pragma unroll
            for (int i = 0; i < 8; i++)
#pragma unroll
                for (int j = 0; j < 8; j++)
                    acc[i][j] += ar[i] * bc[j];
        }
        if (kt < 127) {
            const int nxt = cur ^ 1;
            As[nxt][lk + 0][lr] = av.x; As[nxt][lk + 1][lr] = av.y;
            As[nxt][lk + 2][lr] = av.z; As[nxt][lk + 3][lr] = av.w;
            Bs[nxt][lk + 0][lr] = bv.x; Bs[nxt][lk + 1][lr] = bv.y;
            Bs[nxt][lk + 2][lr] = bv.z; Bs[nxt][lk + 3][lr] = bv.w;
        }
        __syncthreads();
    }

    const float4 bias0 = *(const float4*)&bias[bn * 128 + tx * 4];
    const float4 bias1 = *(const float4*)&bias[bn * 128 + 64 + tx * 4];
#pragma unroll
    for (int i = 0; i < 8; i++) {
        const int gr = bm * 128 + ((i < 4) ? (ty * 4 + i) : (64 + ty * 4 + i - 4));
        float4 o0, o1;
        o0.x = acc[i][0] + bias0.x; o0.y = acc[i][1] + bias0.y;
        o0.z = acc[i][2] + bias0.z; o0.w = acc[i][3] + bias0.w;
        o1.x = acc[i][4] + bias1.x; o1.y = acc[i][5] + bias1.y;
        o1.z = acc[i][6] + bias1.z; o1.w = acc[i][7] + bias1.w;
        *(float4*)&out[(size_t)gr * 4096 + bn * 128 + tx * 4]      = o0;
        *(float4*)&out[(size_t)gr * 4096 + bn * 128 + 64 + tx * 4] = o1;
    }
}

// ---------------------------------------------------------------------------
// Grid barrier per direction (74 CTAs). Sense-reversing, self-resetting:
// counter returns to 0 at every release; phase flips per barrier, and the
// kernel executes an even number of barriers (1 init + 4096 steps + 1 tail
// = 4098), so all global state is restored for the next graph replay.
// ---------------------------------------------------------------------------
__device__ __forceinline__ void gbar(int dir, unsigned &lp)
{
    __threadfence();          // make this thread's h-writes visible (L2)
    __syncthreads();
    if (threadIdx.x == 0) {
        const unsigned np = lp ^ 1u;
        const unsigned old = atomicAdd(&g_count[dir], 1u);
        if (old == (unsigned)(NCTA_DIR - 1)) {
            g_count[dir] = 0u;
            __threadfence();
            g_phase[dir] = np;            // release
        } else {
            while (g_phase[dir] != np) {} // acquire-spin on L2 (volatile)
        }
    }
    __syncthreads();
    __threadfence();
    lp ^= 1u;
}

__device__ __forceinline__ float fsigmoid(float x) {
    return 1.f / (1.f + __expf(-x));
}
__device__ __forceinline__ float ftanh(float x) {
    return 2.f / (1.f + __expf(-2.f * x)) - 1.f;
}

// ---------------------------------------------------------------------------
// Persistent recurrence kernel. 148 CTAs (one wave), 74 per direction.
// Each warp owns one hidden unit: 4 gate rows of Wh resident in SMEM,
// cell state c in a lane-0 register across all 4096 steps.
// ---------------------------------------------------------------------------
__global__ void __launch_bounds__(REC_THREADS, 1) lstm_rec_kernel(
    const float* __restrict__ W0, const float* __restrict__ W1,
    float* __restrict__ out)
{
    extern __shared__ float ws[];
    const int dir  = (blockIdx.x >= NCTA_DIR) ? 1 : 0;
    const int cta  = blockIdx.x - dir * NCTA_DIR;
    const int u0   = cta * UPC;
    const int nu   = (HH - u0 < UPC) ? (HH - u0) : UPC;
    const int tid  = threadIdx.x;
    const int w    = tid >> 5;
    const int lane = tid & 31;
    const float* __restrict__ Wsrc = dir ? W1 : W0;

    // Load this CTA's 56 Wh rows (unit u: rows u, u+H, u+2H, u+3H; cols 0..1023)
    for (int i = tid; i < UPC * 4 * 256; i += REC_THREADS) {
        const int row = i >> 8;        // local row 0..55
        const int f4  = i & 255;       // float4 index within row
        const int ul  = row >> 2;
        const int g   = row & 3;
        float4 v = make_float4(0.f, 0.f, 0.f, 0.f);
        if (ul < nu)
            v = *(const float4*)&Wsrc[(size_t)((g << 10) + u0 + ul) * 2048 + (f4 << 2)];
        *(float4*)&ws[(size_t)row * 1024 + (f4 << 2)] = v;
    }

    const int active = (w < nu);
    const int u = u0 + w;
    if (active && lane == 0) g_h[dir][0][u] = 0.f;

    unsigned lp = 0;
    gbar(dir, lp);   // barrier #1: h0 zeros + (via syncthreads) smem weights ready

    float c = 0.f, hlast = 0.f;
    const float* wrow0 = &ws[(size_t)(w * 4 + 0) * 1024];
    const float* wrow1 = &ws[(size_t)(w * 4 + 1) * 1024];
    const float* wrow2 = &ws[(size_t)(w * 4 + 2) * 1024];
    const float* wrow3 = &ws[(size_t)(w * 4 + 3) * 1024];

    for (int t = 0; t < SS; t++) {
        const int te  = dir ? (SS - 1 - t) : t;
        const int pin = t & 1;

        float x0 = 0.f, x1 = 0.f, x2 = 0.f, x3 = 0.f;
        if (active && lane == 0) {
            const float* xp = &g_xp[dir][te][0];
            x0 = __ldg(xp + u);
            x1 = __ldg(xp + HH + u);
            x2 = __ldg(xp + 2 * HH + u);
            x3 = __ldg(xp + 3 * HH + u);
        }

        if (active) {
            float a0 = 0.f, a1 = 0.f, a2 = 0.f, a3 = 0.f;
            const float4* hp = (const float4*)&g_h[dir][pin][0];
#pragma unroll
            for (int j = 0; j < 8; j++) {
                const int f = j * 32 + lane;           // interleaved: conflict-free LDS.128
                const float4 hv = __ldcg(hp + f);      // MUST bypass L1 (stale-line hazard)
                const float4 v0 = *(const float4*)(wrow0 + 4 * f);
                const float4 v1 = *(const float4*)(wrow1 + 4 * f);
                const float4 v2 = *(const float4*)(wrow2 + 4 * f);
                const float4 v3 = *(const float4*)(wrow3 + 4 * f);
                a0 += v0.x * hv.x + v0.y * hv.y + v0.z * hv.z + v0.w * hv.w;
                a1 += v1.x * hv.x + v1.y * hv.y + v1.z * hv.z + v1.w * hv.w;
                a2 += v2.x * hv.x + v2.y * hv.y + v2.z * hv.z + v2.w * hv.w;
                a3 += v3.x * hv.x + v3.y * hv.y + v3.z * hv.z + v3.w * hv.w;
            }
#pragma unroll
            for (int off = 16; off; off >>= 1) {
                a0 += __shfl_xor_sync(0xffffffffu, a0, off);
                a1 += __shfl_xor_sync(0xffffffffu, a1, off);
                a2 += __shfl_xor_sync(0xffffffffu, a2, off);
                a3 += __shfl_xor_sync(0xffffffffu, a3, off);
            }
            if (lane == 0) {
                const float fg = fsigmoid(a0 + x0);
                const float ig = fsigmoid(a1 + x1);
                const float gg = ftanh(a2 + x2);
                const float og = fsigmoid(a3 + x3);
                c = fg * c + ig * gg;
                const float hv = og * ftanh(c);
                hlast = hv;
                g_h[dir][pin ^ 1][u] = hv;
                out[(size_t)te * 2048 + dir * 1024 + u] = hv;
            }
        }
        gbar(dir, lp);   // step barrier
    }

    if (active && lane == 0)
        out[(size_t)SS * 2048 + dir * 1024 + u] = hlast;

    gbar(dir, lp);       // barrier #4098: restores phase parity for next replay
}

// ---------------------------------------------------------------------------
// kernel_launch: GEMM (both directions) then persistent recurrence.
// Graph-capturable: kernel launches + one attribute set (not a stream op).
// ---------------------------------------------------------------------------
extern "C" void kernel_launch(void* const* d_in, const int* in_sizes, int n_in,
                              void* d_out, int out_size)
{
    const float* inp = (const float*)d_in[0];
    const float* Wf  = (const float*)d_in[1];
    const float* bf  = (const float*)d_in[2];
    const float* Wb  = (const float*)d_in[3];
    const float* bb  = (const float*)d_in[4];
    float* out = (float*)d_out;

    (void)in_sizes; (void)n_in; (void)out_size;

    cudaFuncSetAttribute(lstm_rec_kernel,
                         cudaFuncAttributeMaxDynamicSharedMemorySize, REC_SMEM);

    dim3 ggrid(32, 32, 2);
    xproj_kernel<<<ggrid, 256>>>(inp, Wf, bf, Wb, bb);
    lstm_rec_kernel<<<2 * NCTA_DIR, REC_THREADS, REC_SMEM>>>(Wf, Wb, out);
}